// round 1
// baseline (speedup 1.0000x reference)
#include <cuda_runtime.h>
#include <math.h>

#define BSZ 4
#define DCH 256
#define HC 128
#define WC 128
#define RH 64
#define RW 64
#define RAD 3
#define S2 49
#define CIN0 52
#define HID 32
#define NPIX (HC*WC)

// scratch (static device globals; no runtime allocation)
__device__ float g_q[BSZ*NPIX*DCH];     // normalized upsampled rubin, channels-last (b,p,d)
__device__ float g_k[BSZ*NPIX*DCH];     // normalized vis, channels-last
__device__ float g_x[BSZ*CIN0*NPIX];    // conv input, planar NCHW
__device__ float g_h1[BSZ*HID*NPIX];
__device__ float g_h2[BSZ*HID*NPIX];

__device__ __forceinline__ float wsum32(float v){
#pragma unroll
    for (int o = 16; o; o >>= 1) v += __shfl_xor_sync(0xffffffffu, v, o);
    return v;
}
__device__ __forceinline__ float wmax32(float v){
#pragma unroll
    for (int o = 16; o; o >>= 1) v = fmaxf(v, __shfl_xor_sync(0xffffffffu, v, o));
    return v;
}

// ---------------- K1: bilinear upsample 64->128 (half-pixel) + L2 normalize ----
__global__ __launch_bounds__(256) void k_qprep(const float* __restrict__ rubin){
    int gw = (blockIdx.x*blockDim.x + threadIdx.x) >> 5;
    int lane = threadIdx.x & 31;
    if (gw >= BSZ*NPIX) return;
    int b = gw / NPIX, p = gw % NPIX, y = p / WC, x = p % WC;
    float sy = 0.5f*y - 0.25f, sx = 0.5f*x - 0.25f;
    int y0 = (int)floorf(sy), x0 = (int)floorf(sx);
    float fy = sy - (float)y0, fx = sx - (float)x0;
    int y0c = max(y0, 0), y1c = min(y0+1, RH-1);
    int x0c = max(x0, 0), x1c = min(x0+1, RW-1);
    float w00 = (1.f-fy)*(1.f-fx), w01 = (1.f-fy)*fx, w10 = fy*(1.f-fx), w11 = fy*fx;
    const float* base = rubin + (size_t)b*RH*RW*DCH;
    const float* t00 = base + ((size_t)(y0c*RW + x0c))*DCH + lane*8;
    const float* t01 = base + ((size_t)(y0c*RW + x1c))*DCH + lane*8;
    const float* t10 = base + ((size_t)(y1c*RW + x0c))*DCH + lane*8;
    const float* t11 = base + ((size_t)(y1c*RW + x1c))*DCH + lane*8;
    float4 a0 = *(const float4*)t00, a1 = *(const float4*)(t00+4);
    float4 b0 = *(const float4*)t01, b1 = *(const float4*)(t01+4);
    float4 c0 = *(const float4*)t10, c1 = *(const float4*)(t10+4);
    float4 d0 = *(const float4*)t11, d1 = *(const float4*)(t11+4);
    float v[8];
    v[0] = w00*a0.x + w01*b0.x + w10*c0.x + w11*d0.x;
    v[1] = w00*a0.y + w01*b0.y + w10*c0.y + w11*d0.y;
    v[2] = w00*a0.z + w01*b0.z + w10*c0.z + w11*d0.z;
    v[3] = w00*a0.w + w01*b0.w + w10*c0.w + w11*d0.w;
    v[4] = w00*a1.x + w01*b1.x + w10*c1.x + w11*d1.x;
    v[5] = w00*a1.y + w01*b1.y + w10*c1.y + w11*d1.y;
    v[6] = w00*a1.z + w01*b1.z + w10*c1.z + w11*d1.z;
    v[7] = w00*a1.w + w01*b1.w + w10*c1.w + w11*d1.w;
    float ss = 0.f;
#pragma unroll
    for (int j = 0; j < 8; j++) ss += v[j]*v[j];
    ss = wsum32(ss);
    float inv = 1.f / fmaxf(sqrtf(ss), 1e-12f);
    float* o = g_q + (size_t)gw*DCH + lane*8;
    *(float4*)o     = make_float4(v[0]*inv, v[1]*inv, v[2]*inv, v[3]*inv);
    *(float4*)(o+4) = make_float4(v[4]*inv, v[5]*inv, v[6]*inv, v[7]*inv);
}

// ---------------- K2: L2 normalize vis tokens (already 128x128) ----------------
__global__ __launch_bounds__(256) void k_kprep(const float* __restrict__ vis){
    int gw = (blockIdx.x*blockDim.x + threadIdx.x) >> 5;
    int lane = threadIdx.x & 31;
    if (gw >= BSZ*NPIX) return;
    const float* t = vis + (size_t)gw*DCH + lane*8;
    float4 a0 = *(const float4*)t, a1 = *(const float4*)(t+4);
    float ss = a0.x*a0.x + a0.y*a0.y + a0.z*a0.z + a0.w*a0.w
             + a1.x*a1.x + a1.y*a1.y + a1.z*a1.z + a1.w*a1.w;
    ss = wsum32(ss);
    float inv = 1.f / fmaxf(sqrtf(ss), 1e-12f);
    float* o = g_k + (size_t)gw*DCH + lane*8;
    *(float4*)o     = make_float4(a0.x*inv, a0.y*inv, a0.z*inv, a0.w*inv);
    *(float4*)(o+4) = make_float4(a1.x*inv, a1.y*inv, a1.z*inv, a1.w*inv);
}

// ---------------- K3: correlation volume + soft-argmax ------------------------
// warp per pixel. writes corr/dy/dx/conf into g_x (conv input), and out ch 2,3,4.
__global__ __launch_bounds__(256) void k_corr(const float* __restrict__ log_temp,
                                              float* __restrict__ out){
    __shared__ float sc[8][S2];
    int gw = (blockIdx.x*blockDim.x + threadIdx.x) >> 5;
    int lane = threadIdx.x & 31;
    int wib = threadIdx.x >> 5;
    if (gw >= BSZ*NPIX) return;
    int b = gw / NPIX, p = gw % NPIX, y = p / WC, x = p % WC;

    const float* qv = g_q + (size_t)gw*DCH + lane*8;
    float4 q0 = *(const float4*)qv, q1 = *(const float4*)(qv+4);
    const float* kb = g_k + (size_t)b*NPIX*DCH;

    for (int dy = -RAD; dy <= RAD; dy++){
        int yy = min(max(y+dy, 0), HC-1);
        const float* krow = kb + (size_t)yy*WC*DCH;
#pragma unroll
        for (int dx = -RAD; dx <= RAD; dx++){
            int xx = min(max(x+dx, 0), WC-1);
            const float* kv = krow + (size_t)xx*DCH + lane*8;
            float4 k0 = *(const float4*)kv, k1 = *(const float4*)(kv+4);
            float s = q0.x*k0.x + q0.y*k0.y + q0.z*k0.z + q0.w*k0.w
                    + q1.x*k1.x + q1.y*k1.y + q1.z*k1.z + q1.w*k1.w;
            s = wsum32(s);
            if (lane == 0) sc[wib][(dy+RAD)*7 + (dx+RAD)] = s;
        }
    }
    __syncwarp();

    float temp = expf(log_temp[0]);
    float it = 1.f / temp;
    float c1 = sc[wib][lane];
    float c2 = (lane < S2-32) ? sc[wib][lane+32] : -1e30f;
    float m  = wmax32(fmaxf(c1, c2));
    float e1 = expf((c1 - m) * it);
    float e2 = (lane < S2-32) ? expf((c2 - m) * it) : 0.f;
    float cy1 = (float)(lane/7) - 3.f,      cx1 = (float)(lane%7) - 3.f;
    float cy2 = (float)((lane+32)/7) - 3.f, cx2 = (float)((lane+32)%7) - 3.f;
    float ssum = wsum32(e1 + e2);
    float sy_  = wsum32(e1*cy1 + e2*cy2);
    float sx_  = wsum32(e1*cx1 + e2*cx2);
    float emx  = wmax32(fmaxf(e1, e2));
    float inv  = 1.f / ssum;
    float dyv = sy_*inv, dxv = sx_*inv, conf = emx*inv;

    size_t xb = (size_t)b*CIN0*NPIX;
    g_x[xb + (size_t)(2+lane)*NPIX + p] = c1;
    if (lane < S2-32) g_x[xb + (size_t)(34+lane)*NPIX + p] = c2;
    if (lane == 0){
        g_x[xb + 0*NPIX + p] = dyv;
        g_x[xb + 1*NPIX + p] = dxv;
        g_x[xb + 51*(size_t)NPIX + p] = conf;
        size_t ob = (size_t)b*5*NPIX;
        out[ob + 2*(size_t)NPIX + p] = dyv;
        out[ob + 3*(size_t)NPIX + p] = dxv;
        out[ob + 4*(size_t)NPIX + p] = conf;
    }
}

// ---------------- conv 5x5 SAME, COUT=32, optional exact GELU ------------------
// block: 32x8 output tile; thread (tx, z): 8 rows x 1 col x 4 out-channels
template<int CIN, bool DOGELU>
__global__ __launch_bounds__(256) void k_conv32(const float* __restrict__ in,
                                                float* __restrict__ out,
                                                const float* __restrict__ wt,
                                                const float* __restrict__ bs){
    const int ICCH = 4;
    __shared__ float s_in[ICCH][12][36];
    __shared__ float s_w[ICCH][25][32];
    int tx = threadIdx.x & 31;
    int z  = threadIdx.x >> 5;
    int x0 = blockIdx.x*32, y0 = blockIdx.y*8, b = blockIdx.z;

    float acc[4][8];
#pragma unroll
    for (int i = 0; i < 4; i++)
#pragma unroll
        for (int j = 0; j < 8; j++) acc[i][j] = 0.f;

    for (int cb = 0; cb < CIN; cb += ICCH){
        __syncthreads();
        for (int e = threadIdx.x; e < ICCH*12*36; e += 256){
            int icl = e / (12*36); int rem = e % (12*36);
            int ry = rem / 36, rx = rem % 36;
            int gy = y0 - 2 + ry, gx = x0 - 2 + rx;
            float val = 0.f;
            if (gy >= 0 && gy < HC && gx >= 0 && gx < WC)
                val = in[(((size_t)b*CIN + cb + icl)*HC + gy)*WC + gx];
            s_in[icl][ry][rx] = val;
        }
        for (int e = threadIdx.x; e < ICCH*25*32; e += 256){
            int icl = e / 800; int rem = e % 800;
            int tap = rem / 32, oc = rem % 32;
            s_w[icl][tap][oc] = wt[((size_t)oc*CIN + cb + icl)*25 + tap];
        }
        __syncthreads();
        for (int icl = 0; icl < ICCH; icl++){
            for (int ky = 0; ky < 5; ky++){
#pragma unroll
                for (int kx = 0; kx < 5; kx++){
                    float4 wv = *(const float4*)&s_w[icl][ky*5+kx][z*4];
#pragma unroll
                    for (int yy = 0; yy < 8; yy++){
                        float v = s_in[icl][yy+ky][tx+kx];
                        acc[0][yy] += wv.x * v;
                        acc[1][yy] += wv.y * v;
                        acc[2][yy] += wv.z * v;
                        acc[3][yy] += wv.w * v;
                    }
                }
            }
        }
    }
#pragma unroll
    for (int j = 0; j < 4; j++){
        int oc = z*4 + j;
        float bb = bs[oc];
#pragma unroll
        for (int yy = 0; yy < 8; yy++){
            float val = acc[j][yy] + bb;
            if (DOGELU) val = 0.5f*val*(1.f + erff(val*0.7071067811865476f));
            out[(((size_t)b*32 + oc)*HC + y0 + yy)*WC + x0 + tx] = val;
        }
    }
}

// ---------------- conv2 (32->2) + compose final output -------------------------
__global__ __launch_bounds__(256) void k_conv2_final(const float* __restrict__ h,
                                                     const float* __restrict__ wt,
                                                     const float* __restrict__ bs,
                                                     float* __restrict__ out){
    const int ICCH = 8;
    __shared__ float s_in[ICCH][12][36];
    __shared__ float s_w[HID][25][2];
    int tx = threadIdx.x & 31;
    int z  = threadIdx.x >> 5;
    int x0 = blockIdx.x*32, y0 = blockIdx.y*8, b = blockIdx.z;

    for (int e = threadIdx.x; e < HID*25*2; e += 256){
        int oc = e & 1; int rem = e >> 1;
        int tap = rem % 25; int ic = rem / 25;
        s_w[ic][tap][oc] = wt[((size_t)oc*HID + ic)*25 + tap];
    }

    float a0 = 0.f, a1 = 0.f;
    for (int cb = 0; cb < HID; cb += ICCH){
        __syncthreads();
        for (int e = threadIdx.x; e < ICCH*12*36; e += 256){
            int icl = e / (12*36); int rem = e % (12*36);
            int ry = rem / 36, rx = rem % 36;
            int gy = y0 - 2 + ry, gx = x0 - 2 + rx;
            float val = 0.f;
            if (gy >= 0 && gy < HC && gx >= 0 && gx < WC)
                val = h[(((size_t)b*HID + cb + icl)*HC + gy)*WC + gx];
            s_in[icl][ry][rx] = val;
        }
        __syncthreads();
        for (int icl = 0; icl < ICCH; icl++){
            int ic = cb + icl;
            for (int ky = 0; ky < 5; ky++){
#pragma unroll
                for (int kx = 0; kx < 5; kx++){
                    float2 wv = *(const float2*)&s_w[ic][ky*5+kx][0];
                    float v = s_in[icl][z+ky][tx+kx];
                    a0 += wv.x * v;
                    a1 += wv.y * v;
                }
            }
        }
    }
    int y = y0 + z, x = x0 + tx, p = y*WC + x;
    float r0 = a0 + bs[0];   // residual for dy (channel 0)
    float r1 = a1 + bs[1];   // residual for dx (channel 1)
    size_t xb = (size_t)b*CIN0*NPIX;
    float raw_dy = g_x[xb + 0*NPIX + p];
    float raw_dx = g_x[xb + 1*NPIX + p];
    const float sky = 1.6f;  // 2048 * 0.1 / 128
    size_t ob = (size_t)b*5*NPIX;
    out[ob + 0*(size_t)NPIX + p] = (raw_dx + r1) * sky;  // dra
    out[ob + 1*(size_t)NPIX + p] = (raw_dy + r0) * sky;  // ddec
}

extern "C" void kernel_launch(void* const* d_in, const int* in_sizes, int n_in,
                              void* d_out, int out_size){
    const float* rubin = (const float*)d_in[0];
    const float* vis   = (const float*)d_in[1];
    const float* w0    = (const float*)d_in[2];
    const float* b0    = (const float*)d_in[3];
    const float* w1    = (const float*)d_in[4];
    const float* b1    = (const float*)d_in[5];
    const float* w2    = (const float*)d_in[6];
    const float* b2    = (const float*)d_in[7];
    const float* lt    = (const float*)d_in[8];
    float* out = (float*)d_out;

    float *p_x, *p_h1, *p_h2;
    cudaGetSymbolAddress((void**)&p_x,  g_x);
    cudaGetSymbolAddress((void**)&p_h1, g_h1);
    cudaGetSymbolAddress((void**)&p_h2, g_h2);

    int nwarps = BSZ*NPIX;              // 65536
    k_qprep<<<nwarps/8, 256>>>(rubin);
    k_kprep<<<nwarps/8, 256>>>(vis);
    k_corr <<<nwarps/8, 256>>>(lt, out);

    dim3 g(WC/32, HC/8, BSZ);           // (4,16,4)
    k_conv32<CIN0, true><<<g, 256>>>(p_x,  p_h1, w0, b0);
    k_conv32<HID,  true><<<g, 256>>>(p_h1, p_h2, w1, b1);
    k_conv2_final<<<g, 256>>>(p_h2, w2, b2, out);
}